// round 15
// baseline (speedup 1.0000x reference)
#include <cuda_runtime.h>
#include <math.h>

#define NSTEP 256
#define MAX_RAYS 65536

#define MAGICF   8388608.0f      // 2^23
#define MROUNDF  8388607.5f      // 2^23 - 0.5  (exactly representable)

#define KZ 2                     // output planes per pack block

// Corner-packed grid (64 MB, left L2-resident by pack for the march):
//   g_P[(z<<16)+(y<<8)+x] = uchar4( q(z,y), q(z,y1), q(z1,y), q(z1,y1) ) at this x,
// q(v) = round(sat(v)*255), y1/z1 clamped at the border.
__device__ unsigned g_P[256 * 256 * 256];

// Compacted valid-ray scratch: Ax,Ay,Az,Bx, By,Bz,taufac,pad  (A biased by +1 voxel)
__device__ float g_rayp[MAX_RAYS * 8];
__device__ int   g_ridx[MAX_RAYS];
__device__ int   g_count;

// Quantization via FFMA-magic (no F2I): fmaf(sat(v),255,2^23) puts round(sat(v)*255)
// in the mantissa low byte; PRMT assembles the word. All full-rate fma/alu ops.
__device__ __forceinline__ unsigned q4w(float4 v) {
    float m0 = fmaf(__saturatef(v.x), 255.f, MAGICF);
    float m1 = fmaf(__saturatef(v.y), 255.f, MAGICF);
    float m2 = fmaf(__saturatef(v.z), 255.f, MAGICF);
    float m3 = fmaf(__saturatef(v.w), 255.f, MAGICF);
    unsigned lo = __byte_perm(__float_as_uint(m0), __float_as_uint(m1), 0x0040);
    unsigned hi = __byte_perm(__float_as_uint(m2), __float_as_uint(m3), 0x0040);
    return __byte_perm(lo, hi, 0x5410);   // [q0,q1,q2,q3]
}

// ---------------- Fused pack: fp32 grid -> uchar4 corner grid ----------------
// KZ=2 z-slab per block (3 planes loaded, 2 emitted; 1.55x read amplification).
// __launch_bounds__(256,8) + non-unrolled pass loops keep regs ~32 so all
// 8 blocks/SM fit (64 warps) -> TLP covers load latency (the R14 version
// fully unrolled the loads, hit 64 regs, and stalled at occ 41%).
__global__ void __launch_bounds__(256, 8)
pack_kernel(const float* __restrict__ g)
{
    __shared__ unsigned sm[(KZ + 1) * 33 * 64];   // 25.3 KB

    int t = threadIdx.x;
    if (blockIdx.x == 0 && t == 0) g_count = 0;

    int z0 = (blockIdx.x >> 3) << 1;              // 128 z-slabs of 2
    int y0 = (blockIdx.x & 7) << 5;               // 8 y-tiles of 32 rows

    // Load + quantize 3 planes x 33 rows; minimal live state per iteration
    #pragma unroll 1
    for (int p = 0; p < KZ + 1; ++p) {
        int gz = z0 + p; if (gz > 255) gz = 255;
        const float* gp = g + (gz << 16);
        #pragma unroll 1
        for (int idx = t; idx < 33 * 64; idx += 256) {
            int ry = idx >> 6, xw = idx & 63;
            int gy = y0 + ry; if (gy > 255) gy = 255;
            float4 v = __ldcs(reinterpret_cast<const float4*>(gp + (gy << 8) + (xw << 2)));
            sm[p * (33 * 64) + idx] = q4w(v);
        }
    }
    __syncthreads();

    // Compose + store 2 output planes
    #pragma unroll 1
    for (int p = 0; p < KZ; ++p) {
        #pragma unroll 1
        for (int idx = t; idx < 32 * 64; idx += 256) {
            int r = idx >> 6, xw = idx & 63;
            unsigned a = sm[p * 2112 + r * 64 + xw];             // (z  , y  )
            unsigned b = sm[p * 2112 + (r + 1) * 64 + xw];       // (z  , y+1)
            unsigned c = sm[(p + 1) * 2112 + r * 64 + xw];       // (z+1, y  )
            unsigned d = sm[(p + 1) * 2112 + (r + 1) * 64 + xw]; // (z+1, y+1)

            unsigned outw[4];
            #pragma unroll
            for (int j = 0; j < 4; ++j) {
                unsigned sel = ((4u + j) << 4) | j;
                unsigned lo = __byte_perm(a, b, sel);     // (q00, q01)
                unsigned hi = __byte_perm(c, d, sel);     // (q10, q11)
                outw[j] = __byte_perm(lo, hi, 0x5410);    // (q00,q01,q10,q11)
            }
            uint4 o = make_uint4(outw[0], outw[1], outw[2], outw[3]);

            int gidx = ((z0 + p) << 16) + ((y0 + r) << 8) + (xw << 2);
            *reinterpret_cast<uint4*>(g_P + gidx) = o;    // normal store: stays in L2
        }
    }
}

// ---------------- setup: box test + compaction + biased affine precompute ----------------
__device__ __forceinline__ float safe_inv(float d) {
    const float EPSF = 1e-8f;
    float s = (d > 0.f) ? 1.f : ((d < 0.f) ? -1.f : 0.f);
    float w = (fabsf(d) < EPSF) ? fmaf(s, EPSF, EPSF) : d;
    return 1.0f / w;
}

__global__ void __launch_bounds__(256)
setup_kernel(const float* __restrict__ rays,
             float* __restrict__ out,
             int n_rays)
{
    const float EPSF = 1e-8f;
    int i = blockIdx.x * 256 + threadIdx.x;
    if (i >= n_rays) return;

    const float* r = rays + (size_t)i * 6;
    float ox = __ldg(r + 0), oy = __ldg(r + 1), oz = __ldg(r + 2);
    float dx = __ldg(r + 3), dy = __ldg(r + 4), dz = __ldg(r + 5);

    float nrm = sqrtf(fmaf(dx, dx, fmaf(dy, dy, dz * dz))) + EPSF;
    float inv_n = 1.0f / nrm;
    dx *= inv_n; dy *= inv_n; dz *= inv_n;

    float ixr = safe_inv(dx), iyr = safe_inv(dy), izr = safe_inv(dz);
    float tax = (-1.f - ox) * ixr, tbx = (1.f - ox) * ixr;
    float tay = (-1.f - oy) * iyr, tby = (1.f - oy) * iyr;
    float taz = (-1.f - oz) * izr, tbz = (1.f - oz) * izr;

    float tmin = fmaxf(fmaxf(fminf(tax, tbx), fminf(tay, tby)), fminf(taz, tbz));
    float tmax = fminf(fminf(fmaxf(tax, tbx), fmaxf(tay, tby)), fmaxf(taz, tbz));
    tmin = fmaxf(tmin, 0.0f);

    if (!(tmax > tmin)) {
        out[i] = 1.0f;                    // miss: finished here
        return;
    }
    float seg = tmax - tmin;
    float dt  = seg * (1.0f / (float)NSTEP);
    float t0  = fmaf(0.5f, dt, tmin);     // t at step i=0

    // biased voxel coord g'(i) = (A+1) + i*B per axis
    float dxs = dx * 127.5f, dys = dy * 127.5f, dzs = dz * 127.5f;
    float Ax = fmaf(t0, dxs, (ox + 1.0f) * 127.5f) + 1.0f;
    float Ay = fmaf(t0, dys, (oy + 1.0f) * 127.5f) + 1.0f;
    float Az = fmaf(t0, dzs, (oz + 1.0f) * 127.5f) + 1.0f;
    float Bx = dt * dxs, By = dt * dys, Bz = dt * dzs;

    int slot = atomicAdd(&g_count, 1);
    float* p = g_rayp + (size_t)slot * 8;
    p[0] = Ax; p[1] = Ay; p[2] = Az; p[3] = Bx;
    p[4] = By; p[5] = Bz; p[6] = (10.0f / 255.0f) * dt; p[7] = 0.f;
    g_ridx[slot] = i;
}

// ---------------- march: warp per VALID ray, lane = step index ----------------
// Conversion-free inner loop: magic-rounding for coords, PRMT-magic byte->float.
__global__ void __launch_bounds__(256)
march_kernel(float* __restrict__ out)
{
    int gwarp = (int)((blockIdx.x * 256u + threadIdx.x) >> 5);
    int lane  = threadIdx.x & 31;
    if (gwarp >= g_count) return;         // trailing blocks retire immediately

    const float* p = g_rayp + (size_t)gwarp * 8;
    float4 p0 = *reinterpret_cast<const float4*>(p);
    float4 p1 = *reinterpret_cast<const float4*>(p + 4);
    float Ax = p0.x, Ay = p0.y, Az = p0.z, Bx = p0.w;
    float By = p1.x, Bz = p1.y, taufac = p1.z;

    // bias 1 per axis -> combined index bias 65536+256+1, folded into pointer
    const unsigned* __restrict__ P = g_P - 65793;
    float sum = 0.0f;                     // 0..255 domain
    float fi  = (float)lane;              // step index for this lane

    #pragma unroll 4
    for (int it = 0; it < NSTEP / 32; ++it) {
        float gx = fmaf(fi, Bx, Ax);
        float gy = fmaf(fi, By, Ay);
        float gz = fmaf(fi, Bz, Az);
        fi += 32.0f;

        // magic round: fm = 2^23 + nearest-int(g-0.5); clamp in m-domain
        float fmx = fminf(fmaxf(gx + MROUNDF, MAGICF + 1.f), MAGICF + 255.f);
        float fmy = fminf(fmaxf(gy + MROUNDF, MAGICF + 1.f), MAGICF + 255.f);
        float fmz = fminf(fmaxf(gz + MROUNDF, MAGICF + 1.f), MAGICF + 255.f);

        float fx = gx - (fmx - MAGICF);   // exact
        float fy = gy - (fmy - MAGICF);
        float fz = gz - (fmz - MAGICF);

        // base = (z0<<16)|(y0<<8)|x0 from mantissa bytes: 2 PRMTs, no F2I
        unsigned t01  = __byte_perm(__float_as_uint(fmx), __float_as_uint(fmy), 0x1140);
        unsigned base = __byte_perm(t01, __float_as_uint(fmz), 0x3410);

        unsigned v0 = __ldg(P + base);        // (c000,c010,c100,c110)
        unsigned v1 = __ldg(P + base + 1);    // (c001,c011,c101,c111)

        float m000 = __uint_as_float(__byte_perm(v0, 0x4B000000u, 0x7650));
        float m010 = __uint_as_float(__byte_perm(v0, 0x4B000000u, 0x7651));
        float m100 = __uint_as_float(__byte_perm(v0, 0x4B000000u, 0x7652));
        float m110 = __uint_as_float(__byte_perm(v0, 0x4B000000u, 0x7653));
        float m001 = __uint_as_float(__byte_perm(v1, 0x4B000000u, 0x7650));
        float m011 = __uint_as_float(__byte_perm(v1, 0x4B000000u, 0x7651));
        float m101 = __uint_as_float(__byte_perm(v1, 0x4B000000u, 0x7652));
        float m111 = __uint_as_float(__byte_perm(v1, 0x4B000000u, 0x7653));

        float c00 = fmaf(m001 - m000, fx, m000 - MAGICF);
        float c01 = fmaf(m011 - m010, fx, m010 - MAGICF);
        float c10 = fmaf(m101 - m100, fx, m100 - MAGICF);
        float c11 = fmaf(m111 - m110, fx, m110 - MAGICF);
        float c0  = fmaf(c01 - c00, fy, c00);
        float c1  = fmaf(c11 - c10, fy, c10);
        sum += fmaf(c1 - c0, fz, c0);
    }

    #pragma unroll
    for (int o = 16; o; o >>= 1)
        sum += __shfl_xor_sync(0xffffffffu, sum, o);

    if (lane == 0)
        out[g_ridx[gwarp]] = expf(-taufac * sum);
}

extern "C" void kernel_launch(void* const* d_in, const int* in_sizes, int n_in,
                              void* d_out, int out_size)
{
    const float* rays = (const float*)d_in[0];
    const float* grid = (const float*)d_in[1];
    float* out = (float*)d_out;
    int n_rays = in_sizes[0] / 6;
    if (n_rays > MAX_RAYS) n_rays = MAX_RAYS;

    pack_kernel<<<128 * 8, 256>>>(grid);                 // 2-plane z-slabs, resets g_count
    setup_kernel<<<(n_rays + 255) / 256, 256>>>(rays, out, n_rays);

    int total_threads = n_rays * 32;                     // worst case: all valid
    march_kernel<<<(total_threads + 255) / 256, 256>>>(out);
}

// round 16
// speedup vs baseline: 1.0765x; 1.0765x over previous
#include <cuda_runtime.h>
#include <math.h>

#define NSTEP 256
#define MAX_RAYS 65536

#define MAGICF   8388608.0f      // 2^23
#define MROUNDF  8388607.5f      // 2^23 - 0.5  (exactly representable)

#define KZ 2                     // output planes per pack block

// Corner-packed grid (64 MB, left L2-resident by pack for the march):
//   g_P[(z<<16)+(y<<8)+x] = uchar4( q(z,y), q(z,y1), q(z1,y), q(z1,y1) ) at this x,
// q(v) = round(sat(v)*255), y1/z1 clamped at the border.
__device__ unsigned g_P[256 * 256 * 256];

// Compacted valid-ray scratch: Ax,Ay,Az,Bx, By,Bz,taufac,pad  (A biased by +1 voxel)
__device__ float g_rayp[MAX_RAYS * 8];
__device__ int   g_ridx[MAX_RAYS];
__device__ int   g_count;

// Quantization via FFMA-magic (no F2I): fmaf(sat(v),255,2^23) puts round(sat(v)*255)
// in the mantissa low byte; PRMT assembles the word. All full-rate fma/alu ops.
__device__ __forceinline__ unsigned q4w(float4 v) {
    float m0 = fmaf(__saturatef(v.x), 255.f, MAGICF);
    float m1 = fmaf(__saturatef(v.y), 255.f, MAGICF);
    float m2 = fmaf(__saturatef(v.z), 255.f, MAGICF);
    float m3 = fmaf(__saturatef(v.w), 255.f, MAGICF);
    unsigned lo = __byte_perm(__float_as_uint(m0), __float_as_uint(m1), 0x0040);
    unsigned hi = __byte_perm(__float_as_uint(m2), __float_as_uint(m3), 0x0040);
    return __byte_perm(lo, hi, 0x5410);   // [q0,q1,q2,q3]
}

// ---------------- Fused pack: fp32 grid -> uchar4 corner grid ----------------
// KZ=2 z-slab per block (3 planes loaded, 2 emitted; 1.55x read amplification).
// Load loop iterates positions, fetching all 3 planes per iteration: MLP=3
// with only ~12 regs of load state (R14 got MLP via full unroll -> 64 regs,
// occ 41%; R15 got occ 76% but MLP 1 -> both slower than this middle point).
__global__ void __launch_bounds__(256, 6)
pack_kernel(const float* __restrict__ g)
{
    __shared__ unsigned sm[(KZ + 1) * 33 * 64];   // 25.3 KB

    int t = threadIdx.x;
    if (blockIdx.x == 0 && t == 0) g_count = 0;

    int z0 = (blockIdx.x >> 3) << 1;              // 128 z-slabs of 2
    int y0 = (blockIdx.x & 7) << 5;               // 8 y-tiles of 32 rows
    int z2 = (z0 + 2 < 256) ? z0 + 2 : 255;       // only the top plane can clip

    const float* g0 = g + (z0 << 16);
    const float* g1 = g + ((z0 + 1) << 16);
    const float* g2 = g + (z2 << 16);

    // Load + quantize: per position, 3 independent plane loads in flight
    #pragma unroll 1
    for (int idx = t; idx < 33 * 64; idx += 256) {
        int ry = idx >> 6, xw = idx & 63;
        int gy = y0 + ry; if (gy > 255) gy = 255;
        int off = (gy << 8) + (xw << 2);
        float4 v0 = __ldcs(reinterpret_cast<const float4*>(g0 + off));
        float4 v1 = __ldcs(reinterpret_cast<const float4*>(g1 + off));
        float4 v2 = __ldcs(reinterpret_cast<const float4*>(g2 + off));
        sm[idx]            = q4w(v0);
        sm[2112 + idx]     = q4w(v1);
        sm[2 * 2112 + idx] = q4w(v2);
    }
    __syncthreads();

    // Compose + store 2 output planes
    #pragma unroll 1
    for (int p = 0; p < KZ; ++p) {
        #pragma unroll 1
        for (int idx = t; idx < 32 * 64; idx += 256) {
            int r = idx >> 6, xw = idx & 63;
            unsigned a = sm[p * 2112 + r * 64 + xw];             // (z  , y  )
            unsigned b = sm[p * 2112 + (r + 1) * 64 + xw];       // (z  , y+1)
            unsigned c = sm[(p + 1) * 2112 + r * 64 + xw];       // (z+1, y  )
            unsigned d = sm[(p + 1) * 2112 + (r + 1) * 64 + xw]; // (z+1, y+1)

            unsigned outw[4];
            #pragma unroll
            for (int j = 0; j < 4; ++j) {
                unsigned sel = ((4u + j) << 4) | j;
                unsigned lo = __byte_perm(a, b, sel);     // (q00, q01)
                unsigned hi = __byte_perm(c, d, sel);     // (q10, q11)
                outw[j] = __byte_perm(lo, hi, 0x5410);    // (q00,q01,q10,q11)
            }
            uint4 o = make_uint4(outw[0], outw[1], outw[2], outw[3]);

            int gidx = ((z0 + p) << 16) + ((y0 + r) << 8) + (xw << 2);
            *reinterpret_cast<uint4*>(g_P + gidx) = o;    // normal store: stays in L2
        }
    }
}

// ---------------- setup: box test + compaction + biased affine precompute ----------------
__device__ __forceinline__ float safe_inv(float d) {
    const float EPSF = 1e-8f;
    float s = (d > 0.f) ? 1.f : ((d < 0.f) ? -1.f : 0.f);
    float w = (fabsf(d) < EPSF) ? fmaf(s, EPSF, EPSF) : d;
    return 1.0f / w;
}

__global__ void __launch_bounds__(256)
setup_kernel(const float* __restrict__ rays,
             float* __restrict__ out,
             int n_rays)
{
    const float EPSF = 1e-8f;
    int i = blockIdx.x * 256 + threadIdx.x;
    if (i >= n_rays) return;

    const float* r = rays + (size_t)i * 6;
    float ox = __ldg(r + 0), oy = __ldg(r + 1), oz = __ldg(r + 2);
    float dx = __ldg(r + 3), dy = __ldg(r + 4), dz = __ldg(r + 5);

    float nrm = sqrtf(fmaf(dx, dx, fmaf(dy, dy, dz * dz))) + EPSF;
    float inv_n = 1.0f / nrm;
    dx *= inv_n; dy *= inv_n; dz *= inv_n;

    float ixr = safe_inv(dx), iyr = safe_inv(dy), izr = safe_inv(dz);
    float tax = (-1.f - ox) * ixr, tbx = (1.f - ox) * ixr;
    float tay = (-1.f - oy) * iyr, tby = (1.f - oy) * iyr;
    float taz = (-1.f - oz) * izr, tbz = (1.f - oz) * izr;

    float tmin = fmaxf(fmaxf(fminf(tax, tbx), fminf(tay, tby)), fminf(taz, tbz));
    float tmax = fminf(fminf(fmaxf(tax, tbx), fmaxf(tay, tby)), fmaxf(taz, tbz));
    tmin = fmaxf(tmin, 0.0f);

    if (!(tmax > tmin)) {
        out[i] = 1.0f;                    // miss: finished here
        return;
    }
    float seg = tmax - tmin;
    float dt  = seg * (1.0f / (float)NSTEP);
    float t0  = fmaf(0.5f, dt, tmin);     // t at step i=0

    // biased voxel coord g'(i) = (A+1) + i*B per axis
    float dxs = dx * 127.5f, dys = dy * 127.5f, dzs = dz * 127.5f;
    float Ax = fmaf(t0, dxs, (ox + 1.0f) * 127.5f) + 1.0f;
    float Ay = fmaf(t0, dys, (oy + 1.0f) * 127.5f) + 1.0f;
    float Az = fmaf(t0, dzs, (oz + 1.0f) * 127.5f) + 1.0f;
    float Bx = dt * dxs, By = dt * dys, Bz = dt * dzs;

    int slot = atomicAdd(&g_count, 1);
    float* p = g_rayp + (size_t)slot * 8;
    p[0] = Ax; p[1] = Ay; p[2] = Az; p[3] = Bx;
    p[4] = By; p[5] = Bz; p[6] = (10.0f / 255.0f) * dt; p[7] = 0.f;
    g_ridx[slot] = i;
}

// ---------------- march: warp per VALID ray, lane = step index ----------------
// Conversion-free inner loop: magic-rounding for coords, PRMT-magic byte->float.
__global__ void __launch_bounds__(256)
march_kernel(float* __restrict__ out)
{
    int gwarp = (int)((blockIdx.x * 256u + threadIdx.x) >> 5);
    int lane  = threadIdx.x & 31;
    if (gwarp >= g_count) return;         // trailing blocks retire immediately

    const float* p = g_rayp + (size_t)gwarp * 8;
    float4 p0 = *reinterpret_cast<const float4*>(p);
    float4 p1 = *reinterpret_cast<const float4*>(p + 4);
    float Ax = p0.x, Ay = p0.y, Az = p0.z, Bx = p0.w;
    float By = p1.x, Bz = p1.y, taufac = p1.z;

    // bias 1 per axis -> combined index bias 65536+256+1, folded into pointer
    const unsigned* __restrict__ P = g_P - 65793;
    float sum = 0.0f;                     // 0..255 domain
    float fi  = (float)lane;              // step index for this lane

    #pragma unroll 4
    for (int it = 0; it < NSTEP / 32; ++it) {
        float gx = fmaf(fi, Bx, Ax);
        float gy = fmaf(fi, By, Ay);
        float gz = fmaf(fi, Bz, Az);
        fi += 32.0f;

        // magic round: fm = 2^23 + nearest-int(g-0.5); clamp in m-domain
        float fmx = fminf(fmaxf(gx + MROUNDF, MAGICF + 1.f), MAGICF + 255.f);
        float fmy = fminf(fmaxf(gy + MROUNDF, MAGICF + 1.f), MAGICF + 255.f);
        float fmz = fminf(fmaxf(gz + MROUNDF, MAGICF + 1.f), MAGICF + 255.f);

        float fx = gx - (fmx - MAGICF);   // exact
        float fy = gy - (fmy - MAGICF);
        float fz = gz - (fmz - MAGICF);

        // base = (z0<<16)|(y0<<8)|x0 from mantissa bytes: 2 PRMTs, no F2I
        unsigned t01  = __byte_perm(__float_as_uint(fmx), __float_as_uint(fmy), 0x1140);
        unsigned base = __byte_perm(t01, __float_as_uint(fmz), 0x3410);

        unsigned v0 = __ldg(P + base);        // (c000,c010,c100,c110)
        unsigned v1 = __ldg(P + base + 1);    // (c001,c011,c101,c111)

        float m000 = __uint_as_float(__byte_perm(v0, 0x4B000000u, 0x7650));
        float m010 = __uint_as_float(__byte_perm(v0, 0x4B000000u, 0x7651));
        float m100 = __uint_as_float(__byte_perm(v0, 0x4B000000u, 0x7652));
        float m110 = __uint_as_float(__byte_perm(v0, 0x4B000000u, 0x7653));
        float m001 = __uint_as_float(__byte_perm(v1, 0x4B000000u, 0x7650));
        float m011 = __uint_as_float(__byte_perm(v1, 0x4B000000u, 0x7651));
        float m101 = __uint_as_float(__byte_perm(v1, 0x4B000000u, 0x7652));
        float m111 = __uint_as_float(__byte_perm(v1, 0x4B000000u, 0x7653));

        float c00 = fmaf(m001 - m000, fx, m000 - MAGICF);
        float c01 = fmaf(m011 - m010, fx, m010 - MAGICF);
        float c10 = fmaf(m101 - m100, fx, m100 - MAGICF);
        float c11 = fmaf(m111 - m110, fx, m110 - MAGICF);
        float c0  = fmaf(c01 - c00, fy, c00);
        float c1  = fmaf(c11 - c10, fy, c10);
        sum += fmaf(c1 - c0, fz, c0);
    }

    #pragma unroll
    for (int o = 16; o; o >>= 1)
        sum += __shfl_xor_sync(0xffffffffu, sum, o);

    if (lane == 0)
        out[g_ridx[gwarp]] = expf(-taufac * sum);
}

extern "C" void kernel_launch(void* const* d_in, const int* in_sizes, int n_in,
                              void* d_out, int out_size)
{
    const float* rays = (const float*)d_in[0];
    const float* grid = (const float*)d_in[1];
    float* out = (float*)d_out;
    int n_rays = in_sizes[0] / 6;
    if (n_rays > MAX_RAYS) n_rays = MAX_RAYS;

    pack_kernel<<<128 * 8, 256>>>(grid);                 // 2-plane z-slabs, resets g_count
    setup_kernel<<<(n_rays + 255) / 256, 256>>>(rays, out, n_rays);

    int total_threads = n_rays * 32;                     // worst case: all valid
    march_kernel<<<(total_threads + 255) / 256, 256>>>(out);
}

// round 17
// speedup vs baseline: 1.1457x; 1.0644x over previous
#include <cuda_runtime.h>
#include <math.h>

#define NSTEP 256
#define MAX_RAYS 65536

#define MAGICF   8388608.0f      // 2^23
#define MROUNDF  8388607.5f      // 2^23 - 0.5  (exactly representable)

#define KZ 2                     // output planes per pack block

// Corner-packed grid (64 MB, left L2-resident by pack for the march):
//   g_P[(z<<16)+(y<<8)+x] = uchar4( q(z,y), q(z,y1), q(z1,y), q(z1,y1) ) at this x,
// q(v) = round(sat(v)*255), y1/z1 clamped at the border.
__device__ unsigned g_P[256 * 256 * 256];

// Compacted valid-ray scratch: Ax,Ay,Az,Bx, By,Bz,taufac,pad  (A biased by +1 voxel)
__device__ float g_rayp[MAX_RAYS * 8];
__device__ int   g_ridx[MAX_RAYS];
__device__ int   g_count;        // zeroed by a graph memset node each launch

// Quantization via FFMA-magic (no F2I): fmaf(sat(v),255,2^23) puts round(sat(v)*255)
// in the mantissa low byte; PRMT assembles the word. All full-rate fma/alu ops.
__device__ __forceinline__ unsigned q4w(float4 v) {
    float m0 = fmaf(__saturatef(v.x), 255.f, MAGICF);
    float m1 = fmaf(__saturatef(v.y), 255.f, MAGICF);
    float m2 = fmaf(__saturatef(v.z), 255.f, MAGICF);
    float m3 = fmaf(__saturatef(v.w), 255.f, MAGICF);
    unsigned lo = __byte_perm(__float_as_uint(m0), __float_as_uint(m1), 0x0040);
    unsigned hi = __byte_perm(__float_as_uint(m2), __float_as_uint(m3), 0x0040);
    return __byte_perm(lo, hi, 0x5410);   // [q0,q1,q2,q3]
}

__device__ __forceinline__ float safe_inv(float d) {
    const float EPSF = 1e-8f;
    float s = (d > 0.f) ? 1.f : ((d < 0.f) ? -1.f : 0.f);
    float w = (fabsf(d) < EPSF) ? fmaf(s, EPSF, EPSF) : d;
    return 1.0f / w;
}

// Per-ray setup: box test + compaction + biased affine precompute.
__device__ __forceinline__ void setup_ray(const float* __restrict__ rays,
                                          float* __restrict__ out, int i)
{
    const float EPSF = 1e-8f;
    const float* r = rays + (size_t)i * 6;
    float ox = __ldg(r + 0), oy = __ldg(r + 1), oz = __ldg(r + 2);
    float dx = __ldg(r + 3), dy = __ldg(r + 4), dz = __ldg(r + 5);

    float nrm = sqrtf(fmaf(dx, dx, fmaf(dy, dy, dz * dz))) + EPSF;
    float inv_n = 1.0f / nrm;
    dx *= inv_n; dy *= inv_n; dz *= inv_n;

    float ixr = safe_inv(dx), iyr = safe_inv(dy), izr = safe_inv(dz);
    float tax = (-1.f - ox) * ixr, tbx = (1.f - ox) * ixr;
    float tay = (-1.f - oy) * iyr, tby = (1.f - oy) * iyr;
    float taz = (-1.f - oz) * izr, tbz = (1.f - oz) * izr;

    float tmin = fmaxf(fmaxf(fminf(tax, tbx), fminf(tay, tby)), fminf(taz, tbz));
    float tmax = fminf(fminf(fmaxf(tax, tbx), fmaxf(tay, tby)), fmaxf(taz, tbz));
    tmin = fmaxf(tmin, 0.0f);

    if (!(tmax > tmin)) {
        out[i] = 1.0f;                    // miss: finished here
        return;
    }
    float seg = tmax - tmin;
    float dt  = seg * (1.0f / (float)NSTEP);
    float t0  = fmaf(0.5f, dt, tmin);     // t at step i=0

    // biased voxel coord g'(i) = (A+1) + i*B per axis
    float dxs = dx * 127.5f, dys = dy * 127.5f, dzs = dz * 127.5f;
    float Ax = fmaf(t0, dxs, (ox + 1.0f) * 127.5f) + 1.0f;
    float Ay = fmaf(t0, dys, (oy + 1.0f) * 127.5f) + 1.0f;
    float Az = fmaf(t0, dzs, (oz + 1.0f) * 127.5f) + 1.0f;
    float Bx = dt * dxs, By = dt * dys, Bz = dt * dzs;

    int slot = atomicAdd(&g_count, 1);
    float* p = g_rayp + (size_t)slot * 8;
    p[0] = Ax; p[1] = Ay; p[2] = Az; p[3] = Bx;
    p[4] = By; p[5] = Bz; p[6] = (10.0f / 255.0f) * dt; p[7] = 0.f;
    g_ridx[slot] = i;
}

// ---------------- Fused pack (+ray setup): fp32 grid -> uchar4 corner grid ----------------
// R14-exact pack body (the measured 21.3us config: fully unrolled passes, KZ=2,
// 3 planes loaded / 2 emitted). Ray setup for gtid < n_rays rides along — its
// ALU/atomic work hides inside the pack's memory stalls (issue was only ~30%).
__global__ void __launch_bounds__(256)
pack_kernel(const float* __restrict__ g,
            const float* __restrict__ rays,
            float* __restrict__ out,
            int n_rays)
{
    __shared__ unsigned sm[(KZ + 1) * 33 * 64];   // 25.3 KB

    int t = threadIdx.x;
    int gtid = blockIdx.x * 256 + t;
    if (gtid < n_rays) setup_ray(rays, out, gtid);

    int z0 = (blockIdx.x >> 3) << 1;              // 128 z-slabs of 2
    int y0 = (blockIdx.x & 7) << 5;               // 8 y-tiles of 32 rows

    // Load + quantize 3 planes x 33 rows (fully unrolled: high MLP)
    #pragma unroll
    for (int p = 0; p < KZ + 1; ++p) {
        int gz = z0 + p; if (gz > 255) gz = 255;
        #pragma unroll
        for (int pass = 0; pass < 9; ++pass) {
            int idx = pass * 256 + t;
            if (idx < 33 * 64) {
                int ry = idx >> 6, xw = idx & 63;
                int gy = y0 + ry; if (gy > 255) gy = 255;
                float4 v = __ldcs(reinterpret_cast<const float4*>(
                    g + (((gz << 8) + gy) << 8) + (xw << 2)));
                sm[p * (33 * 64) + idx] = q4w(v);
            }
        }
    }
    __syncthreads();

    // Compose + store 2 output planes
    #pragma unroll
    for (int p = 0; p < KZ; ++p) {
        #pragma unroll
        for (int pass = 0; pass < 8; ++pass) {
            int idx = pass * 256 + t;
            int r = idx >> 6, xw = idx & 63;
            unsigned a = sm[p * 2112 + r * 64 + xw];             // (z  , y  )
            unsigned b = sm[p * 2112 + (r + 1) * 64 + xw];       // (z  , y+1)
            unsigned c = sm[(p + 1) * 2112 + r * 64 + xw];       // (z+1, y  )
            unsigned d = sm[(p + 1) * 2112 + (r + 1) * 64 + xw]; // (z+1, y+1)

            unsigned outw[4];
            #pragma unroll
            for (int j = 0; j < 4; ++j) {
                unsigned sel = ((4u + j) << 4) | j;
                unsigned lo = __byte_perm(a, b, sel);     // (q00, q01)
                unsigned hi = __byte_perm(c, d, sel);     // (q10, q11)
                outw[j] = __byte_perm(lo, hi, 0x5410);    // (q00,q01,q10,q11)
            }
            uint4 o = make_uint4(outw[0], outw[1], outw[2], outw[3]);

            int gidx = ((z0 + p) << 16) + ((y0 + r) << 8) + (xw << 2);
            *reinterpret_cast<uint4*>(g_P + gidx) = o;    // normal store: stays in L2
        }
    }
}

// ---------------- march: warp per VALID ray, lane = step index ----------------
// Conversion-free inner loop: magic-rounding for coords, PRMT-magic byte->float.
__global__ void __launch_bounds__(256)
march_kernel(float* __restrict__ out)
{
    int gwarp = (int)((blockIdx.x * 256u + threadIdx.x) >> 5);
    int lane  = threadIdx.x & 31;
    if (gwarp >= g_count) return;         // trailing blocks retire immediately

    const float* p = g_rayp + (size_t)gwarp * 8;
    float4 p0 = *reinterpret_cast<const float4*>(p);
    float4 p1 = *reinterpret_cast<const float4*>(p + 4);
    float Ax = p0.x, Ay = p0.y, Az = p0.z, Bx = p0.w;
    float By = p1.x, Bz = p1.y, taufac = p1.z;

    // bias 1 per axis -> combined index bias 65536+256+1, folded into pointer
    const unsigned* __restrict__ P = g_P - 65793;
    float sum = 0.0f;                     // 0..255 domain
    float fi  = (float)lane;              // step index for this lane

    #pragma unroll 4
    for (int it = 0; it < NSTEP / 32; ++it) {
        float gx = fmaf(fi, Bx, Ax);
        float gy = fmaf(fi, By, Ay);
        float gz = fmaf(fi, Bz, Az);
        fi += 32.0f;

        // magic round: fm = 2^23 + nearest-int(g-0.5); clamp in m-domain
        float fmx = fminf(fmaxf(gx + MROUNDF, MAGICF + 1.f), MAGICF + 255.f);
        float fmy = fminf(fmaxf(gy + MROUNDF, MAGICF + 1.f), MAGICF + 255.f);
        float fmz = fminf(fmaxf(gz + MROUNDF, MAGICF + 1.f), MAGICF + 255.f);

        float fx = gx - (fmx - MAGICF);   // exact
        float fy = gy - (fmy - MAGICF);
        float fz = gz - (fmz - MAGICF);

        // base = (z0<<16)|(y0<<8)|x0 from mantissa bytes: 2 PRMTs, no F2I
        unsigned t01  = __byte_perm(__float_as_uint(fmx), __float_as_uint(fmy), 0x1140);
        unsigned base = __byte_perm(t01, __float_as_uint(fmz), 0x3410);

        unsigned v0 = __ldg(P + base);        // (c000,c010,c100,c110)
        unsigned v1 = __ldg(P + base + 1);    // (c001,c011,c101,c111)

        float m000 = __uint_as_float(__byte_perm(v0, 0x4B000000u, 0x7650));
        float m010 = __uint_as_float(__byte_perm(v0, 0x4B000000u, 0x7651));
        float m100 = __uint_as_float(__byte_perm(v0, 0x4B000000u, 0x7652));
        float m110 = __uint_as_float(__byte_perm(v0, 0x4B000000u, 0x7653));
        float m001 = __uint_as_float(__byte_perm(v1, 0x4B000000u, 0x7650));
        float m011 = __uint_as_float(__byte_perm(v1, 0x4B000000u, 0x7651));
        float m101 = __uint_as_float(__byte_perm(v1, 0x4B000000u, 0x7652));
        float m111 = __uint_as_float(__byte_perm(v1, 0x4B000000u, 0x7653));

        float c00 = fmaf(m001 - m000, fx, m000 - MAGICF);
        float c01 = fmaf(m011 - m010, fx, m010 - MAGICF);
        float c10 = fmaf(m101 - m100, fx, m100 - MAGICF);
        float c11 = fmaf(m111 - m110, fx, m110 - MAGICF);
        float c0  = fmaf(c01 - c00, fy, c00);
        float c1  = fmaf(c11 - c10, fy, c10);
        sum += fmaf(c1 - c0, fz, c0);
    }

    #pragma unroll
    for (int o = 16; o; o >>= 1)
        sum += __shfl_xor_sync(0xffffffffu, sum, o);

    if (lane == 0)
        out[g_ridx[gwarp]] = expf(-taufac * sum);
}

extern "C" void kernel_launch(void* const* d_in, const int* in_sizes, int n_in,
                              void* d_out, int out_size)
{
    const float* rays = (const float*)d_in[0];
    const float* grid = (const float*)d_in[1];
    float* out = (float*)d_out;
    int n_rays = in_sizes[0] / 6;
    if (n_rays > MAX_RAYS) n_rays = MAX_RAYS;

    // Zero the compaction counter via a (graph-capturable) memset node.
    void* count_ptr = nullptr;
    cudaGetSymbolAddress(&count_ptr, g_count);
    cudaMemsetAsync(count_ptr, 0, sizeof(int));

    // Fused pack + ray setup
    pack_kernel<<<128 * 8, 256>>>(grid, rays, out, n_rays);

    // March: worst case all rays valid; extra blocks exit fast
    int total_threads = n_rays * 32;
    march_kernel<<<(total_threads + 255) / 256, 256>>>(out);
}